// round 3
// baseline (speedup 1.0000x reference)
#include <cuda_runtime.h>
#include <cuda_bf16.h>
#include <cstdint>

#define ROWS 32768
#define H 1024
#define THREADS 256
#define WARPS_PER_BLOCK (THREADS / 32)
#define GRID 296   // 2 blocks per SM on 148 SMs

__global__ void zero_out_kernel(float* __restrict__ out) {
    int i = blockIdx.x * blockDim.x + threadIdx.x;
    if (i < H) out[i] = 0.0f;
}

// Load one key row (8 float4 per lane) with all 8 LDG.128 batched for MLP.
__device__ __forceinline__ void load_row(const float4* __restrict__ k4,
                                         int row, int lane, float4 (&buf)[8]) {
    const float4* kr = k4 + (size_t)row * (H / 4) + lane;
#pragma unroll
    for (int j = 0; j < 8; j++) buf[j] = kr[j * 32];
}

// Reduce one row: dot(q,k), ||k||^2, cosine weight, accumulate c*k into acc.
// q is re-read from smem via asm LDS.128 so ptxas cannot hoist it into
// persistent registers (keeps us at 2 CTAs/SM).
__device__ __forceinline__ void process_row(const float4 (&kv)[8],
                                            float4 (&acc)[8],
                                            uint32_t q_smem_base, int lane,
                                            float inv_qn) {
    float dot = 0.0f, n2 = 0.0f;
#pragma unroll
    for (int j = 0; j < 8; j++) {
        float qx, qy, qz, qw;
        uint32_t addr = q_smem_base + (uint32_t)((j * 32 + lane) * 16);
        asm volatile("ld.shared.v4.f32 {%0,%1,%2,%3}, [%4];"
                     : "=f"(qx), "=f"(qy), "=f"(qz), "=f"(qw) : "r"(addr));
        dot += kv[j].x * qx + kv[j].y * qy + kv[j].z * qz + kv[j].w * qw;
        n2  += kv[j].x * kv[j].x + kv[j].y * kv[j].y
             + kv[j].z * kv[j].z + kv[j].w * kv[j].w;
    }
#pragma unroll
    for (int o = 16; o > 0; o >>= 1) {
        dot += __shfl_xor_sync(0xffffffffu, dot, o);
        n2  += __shfl_xor_sync(0xffffffffu, n2, o);
    }
    const float c = dot * inv_qn * rsqrtf(n2);
#pragma unroll
    for (int j = 0; j < 8; j++) {
        acc[j].x += c * kv[j].x;
        acc[j].y += c * kv[j].y;
        acc[j].z += c * kv[j].z;
        acc[j].w += c * kv[j].w;
    }
}

__global__ __launch_bounds__(THREADS)
void bahdanau_cos_attn_kernel(const float* __restrict__ query,
                              const float* __restrict__ keys,
                              float* __restrict__ out) {
    __shared__ float q_s[H];
    __shared__ float acc_s[H];

    const int tid  = threadIdx.x;
    const int lane = tid & 31;
    const int warp = tid >> 5;

    // Stage q into smem; zero block accumulator.
    for (int i = tid; i < H; i += THREADS) {
        q_s[i] = query[i];
        acc_s[i] = 0.0f;
    }
    __syncthreads();

    const uint32_t q_smem_base = (uint32_t)__cvta_generic_to_shared(q_s);

    // ||q|| (warp-local, deterministic, identical across warps)
    float qn2 = 0.0f;
#pragma unroll
    for (int j = 0; j < 8; j++) {
        const int h = (j * 32 + lane) * 4;
        qn2 += q_s[h] * q_s[h] + q_s[h + 1] * q_s[h + 1]
             + q_s[h + 2] * q_s[h + 2] + q_s[h + 3] * q_s[h + 3];
    }
#pragma unroll
    for (int o = 16; o > 0; o >>= 1) qn2 += __shfl_xor_sync(0xffffffffu, qn2, o);
    const float inv_qn = rsqrtf(qn2);

    float4 acc[8];
#pragma unroll
    for (int j = 0; j < 8; j++) acc[j] = make_float4(0.f, 0.f, 0.f, 0.f);

    const int gwarp  = blockIdx.x * WARPS_PER_BLOCK + warp;
    const int nwarps = gridDim.x * WARPS_PER_BLOCK;
    const float4* k4 = reinterpret_cast<const float4*>(keys);

    // Software-pipelined 2-row double buffer: next row's LDGs issue before
    // the current row's shuffle-reduce tail, keeping loads outstanding ~100%.
    float4 bufA[8], bufB[8];
    int row = gwarp;
    if (row < ROWS) load_row(k4, row, lane, bufA);
    while (row < ROWS) {
        const int rB = row + nwarps;
        if (rB < ROWS) load_row(k4, rB, lane, bufB);
        process_row(bufA, acc, q_smem_base, lane, inv_qn);
        if (rB >= ROWS) break;
        const int rA = rB + nwarps;
        if (rA < ROWS) load_row(k4, rA, lane, bufA);
        process_row(bufB, acc, q_smem_base, lane, inv_qn);
        row = rA;
    }

    // Warp accumulators -> block accumulator (spread-address smem atomics)
#pragma unroll
    for (int j = 0; j < 8; j++) {
        const int h = (j * 32 + lane) * 4;
        atomicAdd(&acc_s[h + 0], acc[j].x);
        atomicAdd(&acc_s[h + 1], acc[j].y);
        atomicAdd(&acc_s[h + 2], acc[j].z);
        atomicAdd(&acc_s[h + 3], acc[j].w);
    }
    __syncthreads();

    // Block accumulator -> global (296 adds per address, spread, cheap)
    for (int i = tid; i < H; i += THREADS) atomicAdd(&out[i], acc_s[i]);
}

extern "C" void kernel_launch(void* const* d_in, const int* in_sizes, int n_in,
                              void* d_out, int out_size) {
    const float* query = (const float*)d_in[0];   // [1, 1024]
    const float* keys  = (const float*)d_in[1];   // [32768, 1024]
    float* out = (float*)d_out;                   // [1, 1024]

    zero_out_kernel<<<(H + 255) / 256, 256>>>(out);
    bahdanau_cos_attn_kernel<<<GRID, THREADS>>>(query, keys, out);
}

// round 10
// speedup vs baseline: 1.0127x; 1.0127x over previous
#include <cuda_runtime.h>
#include <cstdint>

#define ROWS 32768
#define H 1024
#define THREADS 256
#define WARPS_PER_BLOCK (THREADS / 32)
#define STAGES 3
#define GRID 296                 // 2 CTAs per SM on 148 SMs
#define ROW_F4 (H / 4)           // 256 float4 per key row
// dynamic smem: q[H] + acc[H] + WARPS*STAGES rows of H floats
#define SMEM_FLOATS (2 * H + WARPS_PER_BLOCK * STAGES * H)
#define SMEM_BYTES (SMEM_FLOATS * 4)

__global__ void zero_out_kernel(float* __restrict__ out) {
    int i = blockIdx.x * blockDim.x + threadIdx.x;
    if (i < H) out[i] = 0.0f;
}

__device__ __forceinline__ void cp_async16(uint32_t dst_smem, const void* src) {
    asm volatile("cp.async.cg.shared.global [%0], [%1], 16;"
                 :: "r"(dst_smem), "l"(src));
}
__device__ __forceinline__ void cp_commit() {
    asm volatile("cp.async.commit_group;");
}
template <int N>
__device__ __forceinline__ void cp_wait() {
    asm volatile("cp.async.wait_group %0;" :: "n"(N) : "memory");
}

// Issue one key row (4KB) into this warp's smem stage: 8 x 16B cp.async/lane.
__device__ __forceinline__ void issue_row(const float4* __restrict__ k4,
                                          int row, int lane,
                                          uint32_t stage_smem) {
    const float4* src = k4 + (size_t)row * ROW_F4 + lane;
#pragma unroll
    for (int j = 0; j < 8; j++)
        cp_async16(stage_smem + (uint32_t)((j * 32 + lane) * 16),
                   (const void*)(src + j * 32));
}

__global__ __launch_bounds__(THREADS)
void bahdanau_cos_attn_kernel(const float* __restrict__ query,
                              const float* __restrict__ keys,
                              float* __restrict__ out) {
    extern __shared__ float smem[];
    float* q_s   = smem;          // [H]
    float* acc_s = smem + H;      // [H]
    // tiles: warp w, stage s -> smem + 2H + (w*STAGES + s)*H floats

    const int tid  = threadIdx.x;
    const int lane = tid & 31;
    const int warp = tid >> 5;

    for (int i = tid; i < H; i += THREADS) {
        q_s[i]   = query[i];
        acc_s[i] = 0.0f;
    }
    __syncthreads();

    const uint32_t smem_base = (uint32_t)__cvta_generic_to_shared(smem);
    const uint32_t q_base    = smem_base;
    const uint32_t tile_base = smem_base + (uint32_t)(2 * H * 4)
                             + (uint32_t)(warp * STAGES * H * 4);

    // ||q|| (identical in every warp, deterministic)
    float qn2 = 0.0f;
#pragma unroll
    for (int j = 0; j < 8; j++) {
        const int h = (j * 32 + lane) * 4;
        qn2 += q_s[h] * q_s[h] + q_s[h + 1] * q_s[h + 1]
             + q_s[h + 2] * q_s[h + 2] + q_s[h + 3] * q_s[h + 3];
    }
#pragma unroll
    for (int o = 16; o > 0; o >>= 1) qn2 += __shfl_xor_sync(0xffffffffu, qn2, o);
    const float inv_qn = rsqrtf(qn2);

    float4 acc[8];
#pragma unroll
    for (int j = 0; j < 8; j++) acc[j] = make_float4(0.f, 0.f, 0.f, 0.f);

    const int gwarp  = blockIdx.x * WARPS_PER_BLOCK + warp;
    const int nwarps = gridDim.x * WARPS_PER_BLOCK;
    const float4* k4 = reinterpret_cast<const float4*>(keys);

    // Prologue: fill the per-warp pipeline (always commit so group count is
    // uniform; an empty commit_group is legal).
#pragma unroll
    for (int s = 0; s < STAGES; s++) {
        const int r = gwarp + s * nwarps;
        if (r < ROWS) issue_row(k4, r, lane, tile_base + (uint32_t)(s * H * 4));
        cp_commit();
    }

    int stage = 0;
    for (int r = gwarp; r < ROWS; r += nwarps) {
        cp_wait<STAGES - 1>();   // oldest group (this stage) complete
        __syncwarp();

        const uint32_t st = tile_base + (uint32_t)(stage * H * 4);

        // Pull the row from smem into registers (single smem pass).
        float4 kv[8];
#pragma unroll
        for (int j = 0; j < 8; j++) {
            uint32_t a = st + (uint32_t)((j * 32 + lane) * 16);
            asm volatile("ld.shared.v4.f32 {%0,%1,%2,%3}, [%4];"
                         : "=f"(kv[j].x), "=f"(kv[j].y),
                           "=f"(kv[j].z), "=f"(kv[j].w) : "r"(a));
        }

        float dot = 0.0f, n2 = 0.0f;
#pragma unroll
        for (int j = 0; j < 8; j++) {
            float qx, qy, qz, qw;
            uint32_t a = q_base + (uint32_t)((j * 32 + lane) * 16);
            asm volatile("ld.shared.v4.f32 {%0,%1,%2,%3}, [%4];"
                         : "=f"(qx), "=f"(qy), "=f"(qz), "=f"(qw) : "r"(a));
            dot += kv[j].x * qx + kv[j].y * qy + kv[j].z * qz + kv[j].w * qw;
            n2  += kv[j].x * kv[j].x + kv[j].y * kv[j].y
                 + kv[j].z * kv[j].z + kv[j].w * kv[j].w;
        }
#pragma unroll
        for (int o = 16; o > 0; o >>= 1) {
            dot += __shfl_xor_sync(0xffffffffu, dot, o);
            n2  += __shfl_xor_sync(0xffffffffu, n2, o);
        }
        const float c = dot * inv_qn * rsqrtf(n2);
#pragma unroll
        for (int j = 0; j < 8; j++) {
            acc[j].x += c * kv[j].x;
            acc[j].y += c * kv[j].y;
            acc[j].z += c * kv[j].z;
            acc[j].w += c * kv[j].w;
        }

        // Refill this stage with the row STAGES ahead (all LDS above have
        // completed: c depends on every one of them).
        const int rn = r + STAGES * nwarps;
        if (rn < ROWS) issue_row(k4, rn, lane, st);
        cp_commit();

        stage = (stage + 1 == STAGES) ? 0 : stage + 1;
    }

    // Warp accumulators -> block accumulator (spread-address smem atomics)
#pragma unroll
    for (int j = 0; j < 8; j++) {
        const int h = (j * 32 + lane) * 4;
        atomicAdd(&acc_s[h + 0], acc[j].x);
        atomicAdd(&acc_s[h + 1], acc[j].y);
        atomicAdd(&acc_s[h + 2], acc[j].z);
        atomicAdd(&acc_s[h + 3], acc[j].w);
    }
    __syncthreads();

    for (int i = tid; i < H; i += THREADS) atomicAdd(&out[i], acc_s[i]);
}

extern "C" void kernel_launch(void* const* d_in, const int* in_sizes, int n_in,
                              void* d_out, int out_size) {
    const float* query = (const float*)d_in[0];   // [1, 1024]
    const float* keys  = (const float*)d_in[1];   // [32768, 1024]
    float* out = (float*)d_out;                   // [1, 1024]

    cudaFuncSetAttribute(bahdanau_cos_attn_kernel,
                         cudaFuncAttributeMaxDynamicSharedMemorySize, SMEM_BYTES);

    zero_out_kernel<<<(H + 255) / 256, 256>>>(out);
    bahdanau_cos_attn_kernel<<<GRID, THREADS, SMEM_BYTES>>>(query, keys, out);
}